// round 9
// baseline (speedup 1.0000x reference)
#include <cuda_runtime.h>

// Problem constants (static per init_kwargs)
#define N_IMG 8
#define CIN   64
#define H     112
#define W     112
#define HW    (H * W)        // 12544 patches per image (stride 1, pad 1)
#define DPAT  576            // Cin * K * K
#define COUT  64
#define MEM   1025           // memo table size
#define PBIG  HW             // "no patch yet" sentinel for scatter-min

// Scratch (device globals — no allocation allowed)
__device__ double g_csum[N_IMG * HW];          // per-pixel channel sums (exact-ish)
__device__ int    g_bins[N_IMG * HW];          // bin per patch
__device__ int    g_first[N_IMG * MEM];        // first patch index per bin
__device__ float  g_rep[N_IMG * MEM * COUT];   // representative outputs [n][bin][cout]

// ---------------------------------------------------------------------------
// Kernel 1: channel sum per pixel (double accumulation), + re-init g_first.
// fmap layout: [N][CIN][H][W]; warp reads are coalesced (consecutive p).
// ---------------------------------------------------------------------------
__global__ void k_csum(const float* __restrict__ fmap) {
    int gid = blockIdx.x * blockDim.x + threadIdx.x;
    if (gid < N_IMG * MEM) g_first[gid] = PBIG;    // graph-replay-safe init
    if (gid >= N_IMG * HW) return;
    int n = gid / HW;
    int p = gid - n * HW;
    const float* base = fmap + (n * CIN) * HW + p;
    double s = 0.0;
#pragma unroll
    for (int c = 0; c < CIN; ++c)
        s += (double)__ldg(base + c * HW);
    g_csum[gid] = s;
}

// ---------------------------------------------------------------------------
// Kernel 2: 3x3 box sum (zero pad) -> quantized summary -> bin,
// scatter-min of first-occurring patch index.
// Final fp32 ops replicate the reference exactly:
//   mean = f32(sum) / 576.0f ; q = mean * 100.0f ; summ = trunc_to_int(q)
// ---------------------------------------------------------------------------
__global__ void k_bins() {
    int gid = blockIdx.x * blockDim.x + threadIdx.x;
    if (gid >= N_IMG * HW) return;
    int n = gid / HW;
    int p = gid - n * HW;
    int y = p / W;
    int x = p - y * W;
    const double* cs = g_csum + n * HW;

    double s = 0.0;
#pragma unroll
    for (int dy = -1; dy <= 1; ++dy) {
        int yy = y + dy;
        if (yy < 0 || yy >= H) continue;
#pragma unroll
        for (int dx = -1; dx <= 1; ++dx) {
            int xx = x + dx;
            if (xx < 0 || xx >= W) continue;
            s += cs[yy * W + xx];
        }
    }
    float sf   = (float)s;
    float mean = __fdiv_rn(sf, 576.0f);      // IEEE division (immune to fast-math)
    float q    = __fmul_rn(mean, 100.0f);
    int summ   = __float2int_rz(q);          // trunc toward zero == astype(int32)
    int bin    = summ + 512;                 // summ - MIN_SUMMARY
    bin = bin < 0 ? 0 : (bin > MEM - 1 ? MEM - 1 : bin);

    g_bins[gid] = bin;
    atomicMin(&g_first[n * MEM + bin], p);
}

// ---------------------------------------------------------------------------
// Kernel 3: representative GEMM rows. One 64-thread block per (image, bin).
// Inactive bins exit immediately (~400 of 8200 blocks do work).
// Thread t: loads its channel's 3x3 window into SMEM patch (d = c*9+kh*3+kw,
// matching conv_general_dilated_patches / torch-unfold channel-major order),
// then computes output channel t as a 576-length dot with weight row t.
// ---------------------------------------------------------------------------
__global__ void k_rep(const float* __restrict__ fmap,
                      const float* __restrict__ weight,
                      const float* __restrict__ bias) {
    int n = blockIdx.x / MEM;
    int b = blockIdx.x - n * MEM;
    int fp = g_first[n * MEM + b];
    if (fp >= PBIG) return;

    __shared__ float sp[DPAT];
    int t = threadIdx.x;                     // 0..63
    int y = fp / W;
    int x = fp - y * W;

    const float* fb = fmap + (n * CIN + t) * HW;
#pragma unroll
    for (int kh = 0; kh < 3; ++kh) {
        int yy = y + kh - 1;
#pragma unroll
        for (int kw = 0; kw < 3; ++kw) {
            int xx = x + kw - 1;
            float v = 0.0f;
            if (yy >= 0 && yy < H && xx >= 0 && xx < W) v = fb[yy * W + xx];
            sp[t * 9 + kh * 3 + kw] = v;
        }
    }
    __syncthreads();

    const float4* w4 = (const float4*)(weight + t * DPAT);
    const float4* s4 = (const float4*)sp;
    float acc = __ldg(&bias[t]);
#pragma unroll 8
    for (int d = 0; d < DPAT / 4; ++d) {
        float4 wv = __ldg(&w4[d]);
        float4 sv = s4[d];                   // broadcast from SMEM
        acc = fmaf(sv.x, wv.x, acc);
        acc = fmaf(sv.y, wv.y, acc);
        acc = fmaf(sv.z, wv.z, acc);
        acc = fmaf(sv.w, wv.w, acc);
    }
    g_rep[(n * MEM + b) * COUT + t] = acc;   // coalesced, 256B per bin row
}

// ---------------------------------------------------------------------------
// Kernel 4: broadcast representative rows to NCHW output.
// Thread = one patch: float4-reads its bin's 256B row (L2-resident),
// writes are coalesced across the warp for every cout plane.
// ---------------------------------------------------------------------------
__global__ void k_scatter(float* __restrict__ out) {
    int gid = blockIdx.x * blockDim.x + threadIdx.x;
    if (gid >= N_IMG * HW) return;
    int n = gid / HW;
    int p = gid - n * HW;
    int bin = g_bins[gid];

    const float4* r4 = (const float4*)(g_rep + (n * MEM + bin) * COUT);
    float* ob = out + (n * COUT) * HW + p;
#pragma unroll
    for (int i = 0; i < COUT / 4; ++i) {
        float4 v = __ldg(&r4[i]);
        ob[(4 * i + 0) * HW] = v.x;
        ob[(4 * i + 1) * HW] = v.y;
        ob[(4 * i + 2) * HW] = v.z;
        ob[(4 * i + 3) * HW] = v.w;
    }
}

// ---------------------------------------------------------------------------
extern "C" void kernel_launch(void* const* d_in, const int* in_sizes, int n_in,
                              void* d_out, int out_size) {
    const float* fmap   = (const float*)d_in[0];   // [8,64,112,112]
    const float* weight = (const float*)d_in[1];   // [64,576]
    const float* bias   = (const float*)d_in[2];   // [64]
    float* out = (float*)d_out;                    // [8,64,112,112]
    (void)in_sizes; (void)n_in; (void)out_size;

    const int total  = N_IMG * HW;                 // 100352
    const int blocks = (total + 255) / 256;        // 392

    k_csum<<<blocks, 256>>>(fmap);
    k_bins<<<blocks, 256>>>();
    k_rep<<<N_IMG * MEM, COUT>>>(fmap, weight, bias);
    k_scatter<<<blocks, 256>>>(out);
}